// round 16
// baseline (speedup 1.0000x reference)
#include <cuda_runtime.h>
#include <cuda_fp16.h>
#include <math.h>
#include <stdint.h>

#define SEQ   4096
#define EMB   1024
#define NH    16
#define HD    64
#define NE3   3072   // 3*EMB

// Scratch (allocation-free rule: __device__ globals)
__device__ __half g_x_h[SEQ * EMB];     // split x (fp16 hi/lo)
__device__ __half g_x_l[SEQ * EMB];
__device__ __half g_wqkv_h[NE3 * EMB];  // Wqkv^T split [N][K]
__device__ __half g_wqkv_l[NE3 * EMB];
__device__ __half g_wp_h[EMB * EMB];    // Wp^T split [N][K]
__device__ __half g_wp_l[EMB * EMB];
__device__ __half g_qkv_h[SEQ * NE3];   // qkv split
__device__ __half g_qkv_l[SEQ * NE3];
__device__ __half g_att[SEQ * EMB];     // attention out, SINGLE fp16

// ---------------------------------------------------------------------------
// helpers
// ---------------------------------------------------------------------------
__device__ __forceinline__ void mma_f16(float4& d,
    uint32_t a0, uint32_t a1, uint32_t a2, uint32_t a3,
    uint32_t b0, uint32_t b1)
{
    asm("mma.sync.aligned.m16n8k16.row.col.f32.f16.f16.f32 "
        "{%0,%1,%2,%3},{%4,%5,%6,%7},{%8,%9},{%0,%1,%2,%3};\n"
        : "+f"(d.x), "+f"(d.y), "+f"(d.z), "+f"(d.w)
        : "r"(a0), "r"(a1), "r"(a2), "r"(a3), "r"(b0), "r"(b1));
}

// pack (x,y) to half2 word (x in low half)
__device__ __forceinline__ uint32_t pack2h(float x, float y) {
    __half2 h = __floats2half2_rn(x, y);
    return *(uint32_t*)&h;
}
// split (x,y) into fp16 hi and lo words; x ~= hi + lo to ~2^-22 relative
__device__ __forceinline__ void split2h(float x, float y, uint32_t& hi, uint32_t& lo) {
    __half2 h = __floats2half2_rn(x, y);
    float2 hf = __half22float2(h);
    __half2 l = __floats2half2_rn(x - hf.x, y - hf.y);
    hi = *(uint32_t*)&h;
    lo = *(uint32_t*)&l;
}

__device__ __forceinline__ void cp16(uint32_t smem_byte_addr, const void* gptr) {
    asm volatile("cp.async.cg.shared.global [%0], [%1], 16;\n"
                 :: "r"(smem_byte_addr), "l"(gptr));
}
__device__ __forceinline__ void cp_commit() {
    asm volatile("cp.async.commit_group;\n");
}
template<int N>
__device__ __forceinline__ void cp_wait() {
    asm volatile("cp.async.wait_group %0;\n" :: "n"(N));
}

__device__ __forceinline__ void ldsm4(uint32_t& r0, uint32_t& r1,
    uint32_t& r2, uint32_t& r3, uint32_t a)
{
    asm volatile("ldmatrix.sync.aligned.m8n8.x4.shared.b16 {%0,%1,%2,%3},[%4];"
        : "=r"(r0), "=r"(r1), "=r"(r2), "=r"(r3) : "r"(a));
}
__device__ __forceinline__ void ldsm4t(uint32_t& r0, uint32_t& r1,
    uint32_t& r2, uint32_t& r3, uint32_t a)
{
    asm volatile("ldmatrix.sync.aligned.m8n8.x4.trans.shared.b16 {%0,%1,%2,%3},[%4];"
        : "=r"(r0), "=r"(r1), "=r"(r2), "=r"(r3) : "r"(a));
}

// ---------------------------------------------------------------------------
// prep kernels (fp16 variants)
// ---------------------------------------------------------------------------
__global__ __launch_bounds__(256) void split_kernel(
    const float4* __restrict__ src, uint2* __restrict__ hi,
    uint2* __restrict__ lo, int n4)
{
    const int i = blockIdx.x * 256 + threadIdx.x;
    if (i >= n4) return;
    float4 v = src[i];
    uint32_t h0, l0, h1, l1;
    split2h(v.x, v.y, h0, l0);
    split2h(v.z, v.w, h1, l1);
    hi[i] = make_uint2(h0, h1);
    lo[i] = make_uint2(l0, l1);
}

__global__ __launch_bounds__(256) void transpose_split_kernel(
    const float* __restrict__ W, __half* __restrict__ Th,
    __half* __restrict__ Tl, int K, int N)
{
    __shared__ float sm[32][33];
    const int n0 = blockIdx.x * 32;
    const int k0 = blockIdx.y * 32;
    const int tid = threadIdx.x;
    #pragma unroll
    for (int it = 0; it < 4; it++) {
        const int f = tid + it * 256;
        const int r = f >> 5, c = f & 31;
        sm[r][c] = W[(size_t)(k0 + r) * N + n0 + c];
    }
    __syncthreads();
    uint32_t* th = (uint32_t*)Th;
    uint32_t* tl = (uint32_t*)Tl;
    #pragma unroll
    for (int it = 0; it < 2; it++) {
        const int f = tid + it * 256;
        const int n = f >> 4, w = f & 15;
        uint32_t h, l;
        split2h(sm[2 * w][n], sm[2 * w + 1][n], h, l);
        const size_t o = (size_t)(n0 + n) * (K >> 1) + (k0 >> 1) + w;
        th[o] = h;
        tl[o] = l;
    }
}

// ---------------------------------------------------------------------------
// fp16x3 GEMM (QKV): C = A @ Bt^T + bias -> fp16 hi/lo planes
// 128x128x32 tiles, 8 warps 2x4, cp.async 2-stage, ldmatrix, 2 CTAs/SM.
// ---------------------------------------------------------------------------
#define GST 20
#define GEMM_STAGE_WORDS (4 * 128 * GST)
#define GEMM_SMEM (2 * GEMM_STAGE_WORDS * 4)

__global__ __launch_bounds__(256, 2) void gemm_qkv_kernel(
    const __half* __restrict__ Ah, const __half* __restrict__ Al,
    const __half* __restrict__ Bth, const __half* __restrict__ Btl,
    const float* __restrict__ bias,
    __half* __restrict__ Chi, __half* __restrict__ Clo,
    int M, int N, int K)
{
    extern __shared__ uint32_t sm[];
    const uint32_t smb = (uint32_t)__cvta_generic_to_shared(sm);

    const int tid  = threadIdx.x;
    const int w    = tid >> 5;
    const int lane = tid & 31;
    const int g    = lane >> 2;
    const int tg   = lane & 3;
    const int wm   = (w >> 2) * 64;
    const int wn   = (w & 3) * 32;
    const int m_blk = blockIdx.y * 128;
    const int n_blk = blockIdx.x * 128;

    const int lrow0 = tid >> 2;
    const int lu4   = tid & 3;
    const int lcol  = lu4 * 8;

    const int sub = lane >> 3, rr = lane & 7;
    const uint32_t a_lane = ((((sub & 1) * 8 + rr)) * GST + (sub >> 1) * 4) * 4;
    const uint32_t b_lane = ((((sub >> 1) * 8 + rr)) * GST + (sub & 1) * 4) * 4;

    float4 acc[4][4];
    #pragma unroll
    for (int i = 0; i < 4; i++)
        #pragma unroll
        for (int j = 0; j < 4; j++) acc[i][j] = make_float4(0.f, 0.f, 0.f, 0.f);

    const int niter = K / 32;

    auto load_stage = [&](int s, int k0) {
        const uint32_t base = smb + s * GEMM_STAGE_WORDS * 4;
        #pragma unroll
        for (int it = 0; it < 2; it++) {
            const int row = lrow0 + it * 64;
            const uint32_t dst = base + (row * GST + lu4 * 4) * 4;
            const size_t ga = (size_t)(m_blk + row) * K + k0 + lcol;
            const size_t gb = (size_t)(n_blk + row) * K + k0 + lcol;
            cp16(dst,                       Ah + ga);
            cp16(dst + 128 * GST * 4,       Al + ga);
            cp16(dst + 2 * 128 * GST * 4,   Bth + gb);
            cp16(dst + 3 * 128 * GST * 4,   Btl + gb);
        }
    };

    load_stage(0, 0);
    cp_commit();

    for (int i = 0; i < niter; i++) {
        if (i + 1 < niter) {
            load_stage((i + 1) & 1, (i + 1) * 32);
            cp_commit();
            cp_wait<1>();
        } else {
            cp_wait<0>();
        }
        __syncthreads();

        const uint32_t aH = smb + (i & 1) * GEMM_STAGE_WORDS * 4;
        const uint32_t aL = aH + 128 * GST * 4;
        const uint32_t bH = aL + 128 * GST * 4;
        const uint32_t bL = bH + 128 * GST * 4;

        #pragma unroll
        for (int ks = 0; ks < 2; ks++) {
            uint32_t ah[4][4], al[4][4];
            #pragma unroll
            for (int mf = 0; mf < 4; mf++) {
                const uint32_t ao = ((wm + mf * 16) * GST + ks * 8) * 4;
                ldsm4(ah[mf][0], ah[mf][1], ah[mf][2], ah[mf][3], aH + a_lane + ao);
                ldsm4(al[mf][0], al[mf][1], al[mf][2], al[mf][3], aL + a_lane + ao);
            }
            #pragma unroll
            for (int np = 0; np < 2; np++) {
                const uint32_t bo = ((wn + np * 16) * GST + ks * 8) * 4;
                uint32_t b0h, b1h, b2h, b3h, b0l, b1l, b2l, b3l;
                ldsm4(b0h, b1h, b2h, b3h, bH + b_lane + bo);
                ldsm4(b0l, b1l, b2l, b3l, bL + b_lane + bo);
                #pragma unroll
                for (int mf = 0; mf < 4; mf++) {
                    mma_f16(acc[mf][2*np],   ah[mf][0], ah[mf][1], ah[mf][2], ah[mf][3], b0l, b1l);
                    mma_f16(acc[mf][2*np+1], ah[mf][0], ah[mf][1], ah[mf][2], ah[mf][3], b2l, b3l);
                }
                #pragma unroll
                for (int mf = 0; mf < 4; mf++) {
                    mma_f16(acc[mf][2*np],   al[mf][0], al[mf][1], al[mf][2], al[mf][3], b0h, b1h);
                    mma_f16(acc[mf][2*np+1], al[mf][0], al[mf][1], al[mf][2], al[mf][3], b2h, b3h);
                }
                #pragma unroll
                for (int mf = 0; mf < 4; mf++) {
                    mma_f16(acc[mf][2*np],   ah[mf][0], ah[mf][1], ah[mf][2], ah[mf][3], b0h, b1h);
                    mma_f16(acc[mf][2*np+1], ah[mf][0], ah[mf][1], ah[mf][2], ah[mf][3], b2h, b3h);
                }
            }
        }
        __syncthreads();
    }

    #pragma unroll
    for (int nf = 0; nf < 4; nf++) {
        const int c  = n_blk + wn + nf * 8 + 2 * tg;
        const float bc0 = bias[c];
        const float bc1 = bias[c + 1];
        #pragma unroll
        for (int mf = 0; mf < 4; mf++) {
            const int r0 = m_blk + wm + mf * 16 + g;
            const int r1 = r0 + 8;
            uint32_t h, l;
            split2h(acc[mf][nf].x + bc0, acc[mf][nf].y + bc1, h, l);
            ((uint32_t*)Chi)[((size_t)r0 * N + c) >> 1] = h;
            ((uint32_t*)Clo)[((size_t)r0 * N + c) >> 1] = l;
            split2h(acc[mf][nf].z + bc0, acc[mf][nf].w + bc1, h, l);
            ((uint32_t*)Chi)[((size_t)r1 * N + c) >> 1] = h;
            ((uint32_t*)Clo)[((size_t)r1 * N + c) >> 1] = l;
        }
    }
}

// ---------------------------------------------------------------------------
// fp16 2-term GEMM (proj): C = A @ Bt^T + bias, A single fp16, B split.
// Error = A rounding only (~2.8e-4 rel). 3 smem planes, 2 CTAs/SM.
// ---------------------------------------------------------------------------
#define PROJ_STAGE_WORDS (3 * 128 * GST)
#define PROJ_SMEM (2 * PROJ_STAGE_WORDS * 4)

__global__ __launch_bounds__(256, 2) void gemm_proj_kernel(
    const __half* __restrict__ A,
    const __half* __restrict__ Bth, const __half* __restrict__ Btl,
    const float* __restrict__ bias, float* __restrict__ Cf,
    int M, int N, int K)
{
    extern __shared__ uint32_t sm[];
    const uint32_t smb = (uint32_t)__cvta_generic_to_shared(sm);

    const int tid  = threadIdx.x;
    const int w    = tid >> 5;
    const int lane = tid & 31;
    const int g    = lane >> 2;
    const int tg   = lane & 3;
    const int wm   = (w >> 2) * 64;
    const int wn   = (w & 3) * 32;
    const int m_blk = blockIdx.y * 128;
    const int n_blk = blockIdx.x * 128;

    const int lrow0 = tid >> 2;
    const int lu4   = tid & 3;
    const int lcol  = lu4 * 8;

    const int sub = lane >> 3, rr = lane & 7;
    const uint32_t a_lane = ((((sub & 1) * 8 + rr)) * GST + (sub >> 1) * 4) * 4;
    const uint32_t b_lane = ((((sub >> 1) * 8 + rr)) * GST + (sub & 1) * 4) * 4;

    float4 acc[4][4];
    #pragma unroll
    for (int i = 0; i < 4; i++)
        #pragma unroll
        for (int j = 0; j < 4; j++) acc[i][j] = make_float4(0.f, 0.f, 0.f, 0.f);

    const int niter = K / 32;

    auto load_stage = [&](int s, int k0) {
        const uint32_t base = smb + s * PROJ_STAGE_WORDS * 4;
        #pragma unroll
        for (int it = 0; it < 2; it++) {
            const int row = lrow0 + it * 64;
            const uint32_t dst = base + (row * GST + lu4 * 4) * 4;
            const size_t ga = (size_t)(m_blk + row) * K + k0 + lcol;
            const size_t gb = (size_t)(n_blk + row) * K + k0 + lcol;
            cp16(dst,                       A + ga);
            cp16(dst + 128 * GST * 4,       Bth + gb);
            cp16(dst + 2 * 128 * GST * 4,   Btl + gb);
        }
    };

    load_stage(0, 0);
    cp_commit();

    for (int i = 0; i < niter; i++) {
        if (i + 1 < niter) {
            load_stage((i + 1) & 1, (i + 1) * 32);
            cp_commit();
            cp_wait<1>();
        } else {
            cp_wait<0>();
        }
        __syncthreads();

        const uint32_t aH = smb + (i & 1) * PROJ_STAGE_WORDS * 4;
        const uint32_t bH = aH + 128 * GST * 4;
        const uint32_t bL = bH + 128 * GST * 4;

        #pragma unroll
        for (int ks = 0; ks < 2; ks++) {
            uint32_t ah[4][4];
            #pragma unroll
            for (int mf = 0; mf < 4; mf++) {
                const uint32_t ao = ((wm + mf * 16) * GST + ks * 8) * 4;
                ldsm4(ah[mf][0], ah[mf][1], ah[mf][2], ah[mf][3], aH + a_lane + ao);
            }
            #pragma unroll
            for (int np = 0; np < 2; np++) {
                const uint32_t bo = ((wn + np * 16) * GST + ks * 8) * 4;
                uint32_t b0h, b1h, b2h, b3h, b0l, b1l, b2l, b3l;
                ldsm4(b0h, b1h, b2h, b3h, bH + b_lane + bo);
                ldsm4(b0l, b1l, b2l, b3l, bL + b_lane + bo);
                #pragma unroll
                for (int mf = 0; mf < 4; mf++) {
                    mma_f16(acc[mf][2*np],   ah[mf][0], ah[mf][1], ah[mf][2], ah[mf][3], b0l, b1l);
                    mma_f16(acc[mf][2*np+1], ah[mf][0], ah[mf][1], ah[mf][2], ah[mf][3], b2l, b3l);
                }
                #pragma unroll
                for (int mf = 0; mf < 4; mf++) {
                    mma_f16(acc[mf][2*np],   ah[mf][0], ah[mf][1], ah[mf][2], ah[mf][3], b0h, b1h);
                    mma_f16(acc[mf][2*np+1], ah[mf][0], ah[mf][1], ah[mf][2], ah[mf][3], b2h, b3h);
                }
            }
        }
        __syncthreads();
    }

    #pragma unroll
    for (int nf = 0; nf < 4; nf++) {
        const int c  = n_blk + wn + nf * 8 + 2 * tg;
        const float bc0 = bias[c];
        const float bc1 = bias[c + 1];
        #pragma unroll
        for (int mf = 0; mf < 4; mf++) {
            const int r0 = m_blk + wm + mf * 16 + g;
            const int r1 = r0 + 8;
            *(float2*)(Cf + (size_t)r0 * N + c) =
                make_float2(acc[mf][nf].x + bc0, acc[mf][nf].y + bc1);
            *(float2*)(Cf + (size_t)r1 * N + c) =
                make_float2(acc[mf][nf].z + bc0, acc[mf][nf].w + bc1);
        }
    }
}

// ---------------------------------------------------------------------------
// Flash attention, causal, NO 1/sqrt(D) scale. fp16 mma.
// QK: 3-term (hh, hl, lh). PV: 2-term (P single fp16, V split).
// Output: single fp16. Register P; ldmatrix K/V; cp.async double buffer.
// ---------------------------------------------------------------------------
#define KPAD 36
#define KSTAGE (64 * KPAD)
#define ATT_SMEM (8 * KSTAGE * 4)

__global__ __launch_bounds__(256, 2) void flash_attn_f16_kernel(
    const __half* __restrict__ qhi,
    const __half* __restrict__ qlo,
    __half* __restrict__ oatt)
{
    extern __shared__ uint32_t sm[];
    const uint32_t smb = (uint32_t)__cvta_generic_to_shared(sm);

    const int h   = blockIdx.y;
    const int qt  = gridDim.x - 1 - blockIdx.x;
    const int tid = threadIdx.x;
    const int lane = tid & 31;
    const int g    = lane >> 2;
    const int tg   = lane & 3;
    const int m0   = (tid >> 5) * 16;
    const int qbase = qt * 128;

    uint32_t* Qsh = sm;
    uint32_t* Qsl = sm + 128 * KPAD;

    const uint4* qh4 = (const uint4*)qhi;
    const uint4* ql4 = (const uint4*)qlo;

    #pragma unroll
    for (int i = 0; i < 4; i++) {
        const int f   = tid + i * 256;
        const int row = f >> 3;
        const int c   = f & 7;
        const size_t gidx = (size_t)(qbase + row) * 384 + h * 8 + c;
        *(uint4*)&Qsh[row * KPAD + c * 4] = qh4[gidx];
        *(uint4*)&Qsl[row * KPAD + c * 4] = ql4[gidx];
    }
    __syncthreads();

    uint32_t qah[4][4], qal[4][4];
    #pragma unroll
    for (int ks = 0; ks < 4; ks++) {
        const int cp = ks * 8 + tg;
        qah[ks][0] = Qsh[(m0 + g) * KPAD + cp];
        qah[ks][1] = Qsh[(m0 + g + 8) * KPAD + cp];
        qah[ks][2] = Qsh[(m0 + g) * KPAD + cp + 4];
        qah[ks][3] = Qsh[(m0 + g + 8) * KPAD + cp + 4];
        qal[ks][0] = Qsl[(m0 + g) * KPAD + cp];
        qal[ks][1] = Qsl[(m0 + g + 8) * KPAD + cp];
        qal[ks][2] = Qsl[(m0 + g) * KPAD + cp + 4];
        qal[ks][3] = Qsl[(m0 + g + 8) * KPAD + cp + 4];
    }
    __syncthreads();

    const int sub = lane >> 3, rr = lane & 7;
    const uint32_t k_lane = (((sub >> 1) * 8 + rr) * KPAD + (sub & 1) * 4) * 4;
    const uint32_t v_lane = (((sub & 1) * 8 + rr) * KPAD + (sub >> 1) * 4) * 4;

    auto load_kv = [&](int kt, int s) {
        const int kb = kt * 64;
        #pragma unroll
        for (int i = 0; i < 8; i++) {
            const int arr = i >> 1;
            const int c   = tid + (i & 1) * 256;
            const int row = c >> 3;
            const int ch  = c & 7;
            const uint32_t dst = smb +
                ((arr * 2 + s) * KSTAGE + row * KPAD + ch * 4) * 4;
            const size_t off = (size_t)(kb + row) * NE3 + h * 64 + ch * 8 +
                               ((arr >= 2) ? 2 * EMB : EMB);
            const __half* src = (arr & 1) ? qlo : qhi;
            cp16(dst, src + off);
        }
    };

    float4 of[8];
    #pragma unroll
    for (int nf = 0; nf < 8; nf++) of[nf] = make_float4(0.f, 0.f, 0.f, 0.f);
    float mr0 = -INFINITY, mr1 = -INFINITY, lr0 = 0.f, lr1 = 0.f;

    const int nkt = 2 * (qt + 1);
    load_kv(0, 0);
    cp_commit();

    for (int kt = 0; kt < nkt; kt++) {
        const int s = kt & 1;
        if (kt + 1 < nkt) {
            load_kv(kt + 1, s ^ 1);
            cp_commit();
            cp_wait<1>();
        } else {
            cp_wait<0>();
        }
        __syncthreads();

        const uint32_t kh_base = smb + (0 * 2 + s) * KSTAGE * 4;
        const uint32_t kl_base = smb + (1 * 2 + s) * KSTAGE * 4;
        const uint32_t vh_base = smb + (2 * 2 + s) * KSTAGE * 4;
        const uint32_t vl_base = smb + (3 * 2 + s) * KSTAGE * 4;

        // ---- QK^T: S[128 x 64], 3-term fp16, term-major ----
        float4 cf[8];
        #pragma unroll
        for (int nf = 0; nf < 8; nf++) cf[nf] = make_float4(0.f, 0.f, 0.f, 0.f);
        #pragma unroll
        for (int ks = 0; ks < 4; ks++) {
            #pragma unroll
            for (int nph = 0; nph < 2; nph++) {
                const uint32_t off0 = k_lane + (2 * nph) * (16 * KPAD * 4) + ks * 32;
                const uint32_t off1 = off0 + 16 * KPAD * 4;
                uint32_t c0h, c1h, c2h, c3h, c0l, c1l, c2l, c3l;
                uint32_t d0h, d1h, d2h, d3h, d0l, d1l, d2l, d3l;
                ldsm4(c0h, c1h, c2h, c3h, kh_base + off0);
                ldsm4(c0l, c1l, c2l, c3l, kl_base + off0);
                ldsm4(d0h, d1h, d2h, d3h, kh_base + off1);
                ldsm4(d0l, d1l, d2l, d3l, kl_base + off1);
                float4* c4 = &cf[4 * nph];
                mma_f16(c4[0], qah[ks][0], qah[ks][1], qah[ks][2], qah[ks][3], c0l, c1l);
                mma_f16(c4[1], qah[ks][0], qah[ks][1], qah[ks][2], qah[ks][3], c2l, c3l);
                mma_f16(c4[2], qah[ks][0], qah[ks][1], qah[ks][2], qah[ks][3], d0l, d1l);
                mma_f16(c4[3], qah[ks][0], qah[ks][1], qah[ks][2], qah[ks][3], d2l, d3l);
                mma_f16(c4[0], qal[ks][0], qal[ks][1], qal[ks][2], qal[ks][3], c0h, c1h);
                mma_f16(c4[1], qal[ks][0], qal[ks][1], qal[ks][2], qal[ks][3], c2h, c3h);
                mma_f16(c4[2], qal[ks][0], qal[ks][1], qal[ks][2], qal[ks][3], d0h, d1h);
                mma_f16(c4[3], qal[ks][0], qal[ks][1], qal[ks][2], qal[ks][3], d2h, d3h);
                mma_f16(c4[0], qah[ks][0], qah[ks][1], qah[ks][2], qah[ks][3], c0h, c1h);
                mma_f16(c4[1], qah[ks][0], qah[ks][1], qah[ks][2], qah[ks][3], c2h, c3h);
                mma_f16(c4[2], qah[ks][0], qah[ks][1], qah[ks][2], qah[ks][3], d0h, d1h);
                mma_f16(c4[3], qah[ks][0], qah[ks][1], qah[ks][2], qah[ks][3], d2h, d3h);
            }
        }

        // ---- causal mask ----
        const int kb = kt * 64;
        if (kt >= 2 * qt) {
            const int qr0 = qbase + m0 + g;
            const int qr1 = qr0 + 8;
            #pragma unroll
            for (int nf = 0; nf < 8; nf++) {
                const int c0 = kb + nf * 8 + 2 * tg;
                if (c0 > qr0)     cf[nf].x = -INFINITY;
                if (c0 + 1 > qr0) cf[nf].y = -INFINITY;
                if (c0 > qr1)     cf[nf].z = -INFINITY;
                if (c0 + 1 > qr1) cf[nf].w = -INFINITY;
            }
        }

        // ---- row max ----
        float mt0 = -INFINITY, mt1 = -INFINITY;
        #pragma unroll
        for (int nf = 0; nf < 8; nf++) {
            mt0 = fmaxf(mt0, fmaxf(cf[nf].x, cf[nf].y));
            mt1 = fmaxf(mt1, fmaxf(cf[nf].z, cf[nf].w));
        }
        mt0 = fmaxf(mt0, __shfl_xor_sync(0xffffffffu, mt0, 1));
        mt0 = fmaxf(mt0, __shfl_xor_sync(0xffffffffu, mt0, 2));
        mt1 = fmaxf(mt1, __shfl_xor_sync(0xffffffffu, mt1, 1));
        mt1 = fmaxf(mt1, __shfl_xor_sync(0xffffffffu, mt1, 2));

        const float mn0 = fmaxf(mr0, mt0);
        const float mn1 = fmaxf(mr1, mt1);
        const float corr0 = __expf(mr0 - mn0);
        const float corr1 = __expf(mr1 - mn1);
        mr0 = mn0; mr1 = mn1;

        // ---- rescale O ----
        #pragma unroll
        for (int nf = 0; nf < 8; nf++) {
            of[nf].x *= corr0; of[nf].y *= corr0;
            of[nf].z *= corr1; of[nf].w *= corr1;
        }

        // ---- softmax + PV (2-term: P single fp16, V split exact) ----
        float s0 = 0.f, s1 = 0.f;
        #pragma unroll
        for (int ks = 0; ks < 4; ks++) {
            uint32_t ag0, ag1, ag2, ag3;
            {
                const int nf = 2 * ks;
                float p00 = __expf(cf[nf].x - mn0);
                float p01 = __expf(cf[nf].y - mn0);
                float p10 = __expf(cf[nf].z - mn1);
                float p11 = __expf(cf[nf].w - mn1);
                s0 += p00 + p01;  s1 += p10 + p11;
                ag0 = pack2h(p00, p01);
                ag1 = pack2h(p10, p11);
                float q00 = __expf(cf[nf+1].x - mn0);
                float q01 = __expf(cf[nf+1].y - mn0);
                float q10 = __expf(cf[nf+1].z - mn1);
                float q11 = __expf(cf[nf+1].w - mn1);
                s0 += q00 + q01;  s1 += q10 + q11;
                ag2 = pack2h(q00, q01);
                ag3 = pack2h(q10, q11);
            }
            #pragma unroll
            for (int fph = 0; fph < 2; fph++) {
                const uint32_t off0 = v_lane + ks * (16 * KPAD * 4) + (2 * fph) * 32;
                const uint32_t off1 = off0 + 32;
                uint32_t e0h, e1h, e2h, e3h, e0l, e1l, e2l, e3l;
                uint32_t f0h, f1h, f2h, f3h, f0l, f1l, f2l, f3l;
                ldsm4t(e0h, e1h, e2h, e3h, vh_base + off0);
                ldsm4t(e0l, e1l, e2l, e3l, vl_base + off0);
                ldsm4t(f0h, f1h, f2h, f3h, vh_base + off1);
                ldsm4t(f0l, f1l, f2l, f3l, vl_base + off1);
                float4* o4 = &of[4 * fph];
                // term P * V_l
                mma_f16(o4[0], ag0, ag1, ag2, ag3, e0l, e1l);
                mma_f16(o4[1], ag0, ag1, ag2, ag3, e2l, e3l);
                mma_f16(o4[2], ag0, ag1, ag2, ag3, f0l, f1l);
                mma_f16(o4[3], ag0, ag1, ag2, ag3, f2l, f3l);
                // term P * V_h
                mma_f16(o4[0], ag0, ag1, ag2, ag3, e0h, e1h);
                mma_f16(o4[1], ag0, ag1, ag2, ag3, e2h, e3h);
                mma_f16(o4[2], ag0, ag1, ag2, ag3, f0h, f1h);
                mma_f16(o4[3], ag0, ag1, ag2, ag3, f2h, f3h);
            }
        }
        s0 += __shfl_xor_sync(0xffffffffu, s0, 1);
        s0 += __shfl_xor_sync(0xffffffffu, s0, 2);
        s1 += __shfl_xor_sync(0xffffffffu, s1, 1);
        s1 += __shfl_xor_sync(0xffffffffu, s1, 2);
        lr0 = lr0 * corr0 + s0;
        lr1 = lr1 * corr1 + s1;

        __syncthreads();
    }

    // ---- finalize: single fp16 O ----
    const float i0 = 1.f / lr0;
    const float i1 = 1.f / lr1;
    const int r0 = qbase + m0 + g;
    const int r1 = r0 + 8;
    #pragma unroll
    for (int nf = 0; nf < 8; nf++) {
        const int c = h * HD + nf * 8 + 2 * tg;
        ((uint32_t*)oatt)[((size_t)r0 * EMB + c) >> 1] =
            pack2h(of[nf].x * i0, of[nf].y * i0);
        ((uint32_t*)oatt)[((size_t)r1 * EMB + c) >> 1] =
            pack2h(of[nf].z * i1, of[nf].w * i1);
    }
}

// ---------------------------------------------------------------------------
// kernel_launch
// ---------------------------------------------------------------------------
extern "C" void kernel_launch(void* const* d_in, const int* in_sizes, int n_in,
                              void* d_out, int out_size)
{
    const float* x    = (const float*)d_in[0];
    const float* Wqkv = (const float*)d_in[2];
    const float* bqkv = (const float*)d_in[3];
    const float* Wp   = (const float*)d_in[4];
    const float* bp   = (const float*)d_in[5];
    float* out = (float*)d_out;

    __half *xh, *xl, *wqh, *wql, *wph, *wpl, *qkvh, *qkvl, *att;
    cudaGetSymbolAddress((void**)&xh,   g_x_h);
    cudaGetSymbolAddress((void**)&xl,   g_x_l);
    cudaGetSymbolAddress((void**)&wqh,  g_wqkv_h);
    cudaGetSymbolAddress((void**)&wql,  g_wqkv_l);
    cudaGetSymbolAddress((void**)&wph,  g_wp_h);
    cudaGetSymbolAddress((void**)&wpl,  g_wp_l);
    cudaGetSymbolAddress((void**)&qkvh, g_qkv_h);
    cudaGetSymbolAddress((void**)&qkvl, g_qkv_l);
    cudaGetSymbolAddress((void**)&att,  g_att);

    // 0) prep
    split_kernel<<<SEQ * EMB / 4 / 256, 256>>>(
        (const float4*)x, (uint2*)xh, (uint2*)xl, SEQ * EMB / 4);
    {
        dim3 grid(NE3 / 32, EMB / 32);
        transpose_split_kernel<<<grid, 256>>>(Wqkv, wqh, wql, EMB, NE3);
    }
    {
        dim3 grid(EMB / 32, EMB / 32);
        transpose_split_kernel<<<grid, 256>>>(Wp, wph, wpl, EMB, EMB);
    }

    // 1) QKV projection (fp16x3) -> split fp16 qkv
    {
        cudaFuncSetAttribute(gemm_qkv_kernel,
                             cudaFuncAttributeMaxDynamicSharedMemorySize, GEMM_SMEM);
        dim3 grid(NE3 / 128, SEQ / 128);
        gemm_qkv_kernel<<<grid, 256, GEMM_SMEM>>>(
            xh, xl, wqh, wql, bqkv, qkvh, qkvl, SEQ, NE3, EMB);
    }
    // 2) causal flash attention -> single fp16 att
    {
        cudaFuncSetAttribute(flash_attn_f16_kernel,
                             cudaFuncAttributeMaxDynamicSharedMemorySize, ATT_SMEM);
        dim3 grid(SEQ / 128, NH);
        flash_attn_f16_kernel<<<grid, 256, ATT_SMEM>>>(qkvh, qkvl, att);
    }
    // 3) output projection (fp16 2-term) -> f32 out
    {
        cudaFuncSetAttribute(gemm_proj_kernel,
                             cudaFuncAttributeMaxDynamicSharedMemorySize, PROJ_SMEM);
        dim3 grid(EMB / 128, SEQ / 128);
        gemm_proj_kernel<<<grid, 256, PROJ_SMEM>>>(
            att, wph, wpl, bp, out, SEQ, EMB, EMB);
    }
}

// round 17
// speedup vs baseline: 1.0036x; 1.0036x over previous
#include <cuda_runtime.h>
#include <cuda_fp16.h>
#include <math.h>
#include <stdint.h>

#define SEQ   4096
#define EMB   1024
#define NH    16
#define HD    64
#define NE3   3072   // 3*EMB

// Scratch (allocation-free rule: __device__ globals)
__device__ __half g_x_h[SEQ * EMB];     // split x (fp16 hi/lo)
__device__ __half g_x_l[SEQ * EMB];
__device__ __half g_wqkv_h[NE3 * EMB];  // Wqkv^T split [N][K]
__device__ __half g_wqkv_l[NE3 * EMB];
__device__ __half g_wp_h[EMB * EMB];    // Wp^T split [N][K]
__device__ __half g_wp_l[EMB * EMB];
__device__ __half g_qkv_h[SEQ * NE3];   // qkv split
__device__ __half g_qkv_l[SEQ * NE3];
__device__ __half g_att[SEQ * EMB];     // attention out, SINGLE fp16

// ---------------------------------------------------------------------------
// helpers
// ---------------------------------------------------------------------------
__device__ __forceinline__ void mma_f16(float4& d,
    uint32_t a0, uint32_t a1, uint32_t a2, uint32_t a3,
    uint32_t b0, uint32_t b1)
{
    asm("mma.sync.aligned.m16n8k16.row.col.f32.f16.f16.f32 "
        "{%0,%1,%2,%3},{%4,%5,%6,%7},{%8,%9},{%0,%1,%2,%3};\n"
        : "+f"(d.x), "+f"(d.y), "+f"(d.z), "+f"(d.w)
        : "r"(a0), "r"(a1), "r"(a2), "r"(a3), "r"(b0), "r"(b1));
}

// pack (x,y) to half2 word (x in low half)
__device__ __forceinline__ uint32_t pack2h(float x, float y) {
    __half2 h = __floats2half2_rn(x, y);
    return *(uint32_t*)&h;
}
// split (x,y) into fp16 hi and lo words; x ~= hi + lo to ~2^-22 relative
__device__ __forceinline__ void split2h(float x, float y, uint32_t& hi, uint32_t& lo) {
    __half2 h = __floats2half2_rn(x, y);
    float2 hf = __half22float2(h);
    __half2 l = __floats2half2_rn(x - hf.x, y - hf.y);
    hi = *(uint32_t*)&h;
    lo = *(uint32_t*)&l;
}

__device__ __forceinline__ void cp16(uint32_t smem_byte_addr, const void* gptr) {
    asm volatile("cp.async.cg.shared.global [%0], [%1], 16;\n"
                 :: "r"(smem_byte_addr), "l"(gptr));
}
__device__ __forceinline__ void cp_commit() {
    asm volatile("cp.async.commit_group;\n");
}
template<int N>
__device__ __forceinline__ void cp_wait() {
    asm volatile("cp.async.wait_group %0;\n" :: "n"(N));
}

__device__ __forceinline__ void ldsm4(uint32_t& r0, uint32_t& r1,
    uint32_t& r2, uint32_t& r3, uint32_t a)
{
    asm volatile("ldmatrix.sync.aligned.m8n8.x4.shared.b16 {%0,%1,%2,%3},[%4];"
        : "=r"(r0), "=r"(r1), "=r"(r2), "=r"(r3) : "r"(a));
}
__device__ __forceinline__ void ldsm4t(uint32_t& r0, uint32_t& r1,
    uint32_t& r2, uint32_t& r3, uint32_t a)
{
    asm volatile("ldmatrix.sync.aligned.m8n8.x4.trans.shared.b16 {%0,%1,%2,%3},[%4];"
        : "=r"(r0), "=r"(r1), "=r"(r2), "=r"(r3) : "r"(a));
}

// ---------------------------------------------------------------------------
// prep kernels (fp16 variants)
// ---------------------------------------------------------------------------
__global__ __launch_bounds__(256) void split_kernel(
    const float4* __restrict__ src, uint2* __restrict__ hi,
    uint2* __restrict__ lo, int n4)
{
    const int i = blockIdx.x * 256 + threadIdx.x;
    if (i >= n4) return;
    float4 v = src[i];
    uint32_t h0, l0, h1, l1;
    split2h(v.x, v.y, h0, l0);
    split2h(v.z, v.w, h1, l1);
    hi[i] = make_uint2(h0, h1);
    lo[i] = make_uint2(l0, l1);
}

__global__ __launch_bounds__(256) void transpose_split_kernel(
    const float* __restrict__ W, __half* __restrict__ Th,
    __half* __restrict__ Tl, int K, int N)
{
    __shared__ float sm[32][33];
    const int n0 = blockIdx.x * 32;
    const int k0 = blockIdx.y * 32;
    const int tid = threadIdx.x;
    #pragma unroll
    for (int it = 0; it < 4; it++) {
        const int f = tid + it * 256;
        const int r = f >> 5, c = f & 31;
        sm[r][c] = W[(size_t)(k0 + r) * N + n0 + c];
    }
    __syncthreads();
    uint32_t* th = (uint32_t*)Th;
    uint32_t* tl = (uint32_t*)Tl;
    #pragma unroll
    for (int it = 0; it < 2; it++) {
        const int f = tid + it * 256;
        const int n = f >> 4, w = f & 15;
        uint32_t h, l;
        split2h(sm[2 * w][n], sm[2 * w + 1][n], h, l);
        const size_t o = (size_t)(n0 + n) * (K >> 1) + (k0 >> 1) + w;
        th[o] = h;
        tl[o] = l;
    }
}

// ---------------------------------------------------------------------------
// fp16x3 GEMM (QKV): C = A @ Bt^T + bias -> fp16 hi/lo planes
// 128x128x32 tiles, 8 warps 2x4, cp.async 2-stage, ldmatrix, 2 CTAs/SM.
// ---------------------------------------------------------------------------
#define GST 20
#define GEMM_STAGE_WORDS (4 * 128 * GST)
#define GEMM_SMEM (2 * GEMM_STAGE_WORDS * 4)

__global__ __launch_bounds__(256, 2) void gemm_qkv_kernel(
    const __half* __restrict__ Ah, const __half* __restrict__ Al,
    const __half* __restrict__ Bth, const __half* __restrict__ Btl,
    const float* __restrict__ bias,
    __half* __restrict__ Chi, __half* __restrict__ Clo,
    int M, int N, int K)
{
    extern __shared__ uint32_t sm[];
    const uint32_t smb = (uint32_t)__cvta_generic_to_shared(sm);

    const int tid  = threadIdx.x;
    const int w    = tid >> 5;
    const int lane = tid & 31;
    const int g    = lane >> 2;
    const int tg   = lane & 3;
    const int wm   = (w >> 2) * 64;
    const int wn   = (w & 3) * 32;
    const int m_blk = blockIdx.y * 128;
    const int n_blk = blockIdx.x * 128;

    const int lrow0 = tid >> 2;
    const int lu4   = tid & 3;
    const int lcol  = lu4 * 8;

    const int sub = lane >> 3, rr = lane & 7;
    const uint32_t a_lane = ((((sub & 1) * 8 + rr)) * GST + (sub >> 1) * 4) * 4;
    const uint32_t b_lane = ((((sub >> 1) * 8 + rr)) * GST + (sub & 1) * 4) * 4;

    float4 acc[4][4];
    #pragma unroll
    for (int i = 0; i < 4; i++)
        #pragma unroll
        for (int j = 0; j < 4; j++) acc[i][j] = make_float4(0.f, 0.f, 0.f, 0.f);

    const int niter = K / 32;

    auto load_stage = [&](int s, int k0) {
        const uint32_t base = smb + s * GEMM_STAGE_WORDS * 4;
        #pragma unroll
        for (int it = 0; it < 2; it++) {
            const int row = lrow0 + it * 64;
            const uint32_t dst = base + (row * GST + lu4 * 4) * 4;
            const size_t ga = (size_t)(m_blk + row) * K + k0 + lcol;
            const size_t gb = (size_t)(n_blk + row) * K + k0 + lcol;
            cp16(dst,                       Ah + ga);
            cp16(dst + 128 * GST * 4,       Al + ga);
            cp16(dst + 2 * 128 * GST * 4,   Bth + gb);
            cp16(dst + 3 * 128 * GST * 4,   Btl + gb);
        }
    };

    load_stage(0, 0);
    cp_commit();

    for (int i = 0; i < niter; i++) {
        if (i + 1 < niter) {
            load_stage((i + 1) & 1, (i + 1) * 32);
            cp_commit();
            cp_wait<1>();
        } else {
            cp_wait<0>();
        }
        __syncthreads();

        const uint32_t aH = smb + (i & 1) * GEMM_STAGE_WORDS * 4;
        const uint32_t aL = aH + 128 * GST * 4;
        const uint32_t bH = aL + 128 * GST * 4;
        const uint32_t bL = bH + 128 * GST * 4;

        #pragma unroll
        for (int ks = 0; ks < 2; ks++) {
            uint32_t ah[4][4], al[4][4];
            #pragma unroll
            for (int mf = 0; mf < 4; mf++) {
                const uint32_t ao = ((wm + mf * 16) * GST + ks * 8) * 4;
                ldsm4(ah[mf][0], ah[mf][1], ah[mf][2], ah[mf][3], aH + a_lane + ao);
                ldsm4(al[mf][0], al[mf][1], al[mf][2], al[mf][3], aL + a_lane + ao);
            }
            #pragma unroll
            for (int np = 0; np < 2; np++) {
                const uint32_t bo = ((wn + np * 16) * GST + ks * 8) * 4;
                uint32_t b0h, b1h, b2h, b3h, b0l, b1l, b2l, b3l;
                ldsm4(b0h, b1h, b2h, b3h, bH + b_lane + bo);
                ldsm4(b0l, b1l, b2l, b3l, bL + b_lane + bo);
                #pragma unroll
                for (int mf = 0; mf < 4; mf++) {
                    mma_f16(acc[mf][2*np],   ah[mf][0], ah[mf][1], ah[mf][2], ah[mf][3], b0l, b1l);
                    mma_f16(acc[mf][2*np+1], ah[mf][0], ah[mf][1], ah[mf][2], ah[mf][3], b2l, b3l);
                }
                #pragma unroll
                for (int mf = 0; mf < 4; mf++) {
                    mma_f16(acc[mf][2*np],   al[mf][0], al[mf][1], al[mf][2], al[mf][3], b0h, b1h);
                    mma_f16(acc[mf][2*np+1], al[mf][0], al[mf][1], al[mf][2], al[mf][3], b2h, b3h);
                }
                #pragma unroll
                for (int mf = 0; mf < 4; mf++) {
                    mma_f16(acc[mf][2*np],   ah[mf][0], ah[mf][1], ah[mf][2], ah[mf][3], b0h, b1h);
                    mma_f16(acc[mf][2*np+1], ah[mf][0], ah[mf][1], ah[mf][2], ah[mf][3], b2h, b3h);
                }
            }
        }
        __syncthreads();
    }

    #pragma unroll
    for (int nf = 0; nf < 4; nf++) {
        const int c  = n_blk + wn + nf * 8 + 2 * tg;
        const float bc0 = bias[c];
        const float bc1 = bias[c + 1];
        #pragma unroll
        for (int mf = 0; mf < 4; mf++) {
            const int r0 = m_blk + wm + mf * 16 + g;
            const int r1 = r0 + 8;
            uint32_t h, l;
            split2h(acc[mf][nf].x + bc0, acc[mf][nf].y + bc1, h, l);
            ((uint32_t*)Chi)[((size_t)r0 * N + c) >> 1] = h;
            ((uint32_t*)Clo)[((size_t)r0 * N + c) >> 1] = l;
            split2h(acc[mf][nf].z + bc0, acc[mf][nf].w + bc1, h, l);
            ((uint32_t*)Chi)[((size_t)r1 * N + c) >> 1] = h;
            ((uint32_t*)Clo)[((size_t)r1 * N + c) >> 1] = l;
        }
    }
}

// ---------------------------------------------------------------------------
// fp16 2-term GEMM (proj): C = A @ Bt^T + bias, A single fp16, B split.
// Error = A rounding only (~2.8e-4 rel). 3 smem planes, 2 CTAs/SM.
// ---------------------------------------------------------------------------
#define PROJ_STAGE_WORDS (3 * 128 * GST)
#define PROJ_SMEM (2 * PROJ_STAGE_WORDS * 4)

__global__ __launch_bounds__(256, 2) void gemm_proj_kernel(
    const __half* __restrict__ A,
    const __half* __restrict__ Bth, const __half* __restrict__ Btl,
    const float* __restrict__ bias, float* __restrict__ Cf,
    int M, int N, int K)
{
    extern __shared__ uint32_t sm[];
    const uint32_t smb = (uint32_t)__cvta_generic_to_shared(sm);

    const int tid  = threadIdx.x;
    const int w    = tid >> 5;
    const int lane = tid & 31;
    const int g    = lane >> 2;
    const int tg   = lane & 3;
    const int wm   = (w >> 2) * 64;
    const int wn   = (w & 3) * 32;
    const int m_blk = blockIdx.y * 128;
    const int n_blk = blockIdx.x * 128;

    const int lrow0 = tid >> 2;
    const int lu4   = tid & 3;
    const int lcol  = lu4 * 8;

    const int sub = lane >> 3, rr = lane & 7;
    const uint32_t a_lane = ((((sub & 1) * 8 + rr)) * GST + (sub >> 1) * 4) * 4;
    const uint32_t b_lane = ((((sub >> 1) * 8 + rr)) * GST + (sub & 1) * 4) * 4;

    float4 acc[4][4];
    #pragma unroll
    for (int i = 0; i < 4; i++)
        #pragma unroll
        for (int j = 0; j < 4; j++) acc[i][j] = make_float4(0.f, 0.f, 0.f, 0.f);

    const int niter = K / 32;

    auto load_stage = [&](int s, int k0) {
        const uint32_t base = smb + s * PROJ_STAGE_WORDS * 4;
        #pragma unroll
        for (int it = 0; it < 2; it++) {
            const int row = lrow0 + it * 64;
            const uint32_t dst = base + (row * GST + lu4 * 4) * 4;
            const size_t ga = (size_t)(m_blk + row) * K + k0 + lcol;
            const size_t gb = (size_t)(n_blk + row) * K + k0 + lcol;
            cp16(dst,                       A + ga);
            cp16(dst + 128 * GST * 4,       Bth + gb);
            cp16(dst + 2 * 128 * GST * 4,   Btl + gb);
        }
    };

    load_stage(0, 0);
    cp_commit();

    for (int i = 0; i < niter; i++) {
        if (i + 1 < niter) {
            load_stage((i + 1) & 1, (i + 1) * 32);
            cp_commit();
            cp_wait<1>();
        } else {
            cp_wait<0>();
        }
        __syncthreads();

        const uint32_t aH = smb + (i & 1) * PROJ_STAGE_WORDS * 4;
        const uint32_t bH = aH + 128 * GST * 4;
        const uint32_t bL = bH + 128 * GST * 4;

        #pragma unroll
        for (int ks = 0; ks < 2; ks++) {
            uint32_t ah[4][4];
            #pragma unroll
            for (int mf = 0; mf < 4; mf++) {
                const uint32_t ao = ((wm + mf * 16) * GST + ks * 8) * 4;
                ldsm4(ah[mf][0], ah[mf][1], ah[mf][2], ah[mf][3], aH + a_lane + ao);
            }
            #pragma unroll
            for (int np = 0; np < 2; np++) {
                const uint32_t bo = ((wn + np * 16) * GST + ks * 8) * 4;
                uint32_t b0h, b1h, b2h, b3h, b0l, b1l, b2l, b3l;
                ldsm4(b0h, b1h, b2h, b3h, bH + b_lane + bo);
                ldsm4(b0l, b1l, b2l, b3l, bL + b_lane + bo);
                #pragma unroll
                for (int mf = 0; mf < 4; mf++) {
                    mma_f16(acc[mf][2*np],   ah[mf][0], ah[mf][1], ah[mf][2], ah[mf][3], b0l, b1l);
                    mma_f16(acc[mf][2*np+1], ah[mf][0], ah[mf][1], ah[mf][2], ah[mf][3], b2l, b3l);
                }
                #pragma unroll
                for (int mf = 0; mf < 4; mf++) {
                    mma_f16(acc[mf][2*np],   ah[mf][0], ah[mf][1], ah[mf][2], ah[mf][3], b0h, b1h);
                    mma_f16(acc[mf][2*np+1], ah[mf][0], ah[mf][1], ah[mf][2], ah[mf][3], b2h, b3h);
                }
            }
        }
        __syncthreads();
    }

    #pragma unroll
    for (int nf = 0; nf < 4; nf++) {
        const int c  = n_blk + wn + nf * 8 + 2 * tg;
        const float bc0 = bias[c];
        const float bc1 = bias[c + 1];
        #pragma unroll
        for (int mf = 0; mf < 4; mf++) {
            const int r0 = m_blk + wm + mf * 16 + g;
            const int r1 = r0 + 8;
            *(float2*)(Cf + (size_t)r0 * N + c) =
                make_float2(acc[mf][nf].x + bc0, acc[mf][nf].y + bc1);
            *(float2*)(Cf + (size_t)r1 * N + c) =
                make_float2(acc[mf][nf].z + bc0, acc[mf][nf].w + bc1);
        }
    }
}

// ---------------------------------------------------------------------------
// Flash attention, causal, NO 1/sqrt(D) scale. fp16 mma.
// QK: 3-term (hh, hl, lh). PV: 2-term (P single fp16, V split).
// Output: single fp16. Register P; ldmatrix K/V; cp.async double buffer.
// ---------------------------------------------------------------------------
#define KPAD 36
#define KSTAGE (64 * KPAD)
#define ATT_SMEM (8 * KSTAGE * 4)

__global__ __launch_bounds__(256, 2) void flash_attn_f16_kernel(
    const __half* __restrict__ qhi,
    const __half* __restrict__ qlo,
    __half* __restrict__ oatt)
{
    extern __shared__ uint32_t sm[];
    const uint32_t smb = (uint32_t)__cvta_generic_to_shared(sm);

    const int h   = blockIdx.y;
    const int qt  = gridDim.x - 1 - blockIdx.x;
    const int tid = threadIdx.x;
    const int lane = tid & 31;
    const int g    = lane >> 2;
    const int tg   = lane & 3;
    const int m0   = (tid >> 5) * 16;
    const int qbase = qt * 128;

    uint32_t* Qsh = sm;
    uint32_t* Qsl = sm + 128 * KPAD;

    const uint4* qh4 = (const uint4*)qhi;
    const uint4* ql4 = (const uint4*)qlo;

    #pragma unroll
    for (int i = 0; i < 4; i++) {
        const int f   = tid + i * 256;
        const int row = f >> 3;
        const int c   = f & 7;
        const size_t gidx = (size_t)(qbase + row) * 384 + h * 8 + c;
        *(uint4*)&Qsh[row * KPAD + c * 4] = qh4[gidx];
        *(uint4*)&Qsl[row * KPAD + c * 4] = ql4[gidx];
    }
    __syncthreads();

    uint32_t qah[4][4], qal[4][4];
    #pragma unroll
    for (int ks = 0; ks < 4; ks++) {
        const int cp = ks * 8 + tg;
        qah[ks][0] = Qsh[(m0 + g) * KPAD + cp];
        qah[ks][1] = Qsh[(m0 + g + 8) * KPAD + cp];
        qah[ks][2] = Qsh[(m0 + g) * KPAD + cp + 4];
        qah[ks][3] = Qsh[(m0 + g + 8) * KPAD + cp + 4];
        qal[ks][0] = Qsl[(m0 + g) * KPAD + cp];
        qal[ks][1] = Qsl[(m0 + g + 8) * KPAD + cp];
        qal[ks][2] = Qsl[(m0 + g) * KPAD + cp + 4];
        qal[ks][3] = Qsl[(m0 + g + 8) * KPAD + cp + 4];
    }
    __syncthreads();

    const int sub = lane >> 3, rr = lane & 7;
    const uint32_t k_lane = (((sub >> 1) * 8 + rr) * KPAD + (sub & 1) * 4) * 4;
    const uint32_t v_lane = (((sub & 1) * 8 + rr) * KPAD + (sub >> 1) * 4) * 4;

    auto load_kv = [&](int kt, int s) {
        const int kb = kt * 64;
        #pragma unroll
        for (int i = 0; i < 8; i++) {
            const int arr = i >> 1;
            const int c   = tid + (i & 1) * 256;
            const int row = c >> 3;
            const int ch  = c & 7;
            const uint32_t dst = smb +
                ((arr * 2 + s) * KSTAGE + row * KPAD + ch * 4) * 4;
            const size_t off = (size_t)(kb + row) * NE3 + h * 64 + ch * 8 +
                               ((arr >= 2) ? 2 * EMB : EMB);
            const __half* src = (arr & 1) ? qlo : qhi;
            cp16(dst, src + off);
        }
    };

    float4 of[8];
    #pragma unroll
    for (int nf = 0; nf < 8; nf++) of[nf] = make_float4(0.f, 0.f, 0.f, 0.f);
    float mr0 = -INFINITY, mr1 = -INFINITY, lr0 = 0.f, lr1 = 0.f;

    const int nkt = 2 * (qt + 1);
    load_kv(0, 0);
    cp_commit();

    for (int kt = 0; kt < nkt; kt++) {
        const int s = kt & 1;
        if (kt + 1 < nkt) {
            load_kv(kt + 1, s ^ 1);
            cp_commit();
            cp_wait<1>();
        } else {
            cp_wait<0>();
        }
        __syncthreads();

        const uint32_t kh_base = smb + (0 * 2 + s) * KSTAGE * 4;
        const uint32_t kl_base = smb + (1 * 2 + s) * KSTAGE * 4;
        const uint32_t vh_base = smb + (2 * 2 + s) * KSTAGE * 4;
        const uint32_t vl_base = smb + (3 * 2 + s) * KSTAGE * 4;

        // ---- QK^T: S[128 x 64], 3-term fp16, term-major ----
        float4 cf[8];
        #pragma unroll
        for (int nf = 0; nf < 8; nf++) cf[nf] = make_float4(0.f, 0.f, 0.f, 0.f);
        #pragma unroll
        for (int ks = 0; ks < 4; ks++) {
            #pragma unroll
            for (int nph = 0; nph < 2; nph++) {
                const uint32_t off0 = k_lane + (2 * nph) * (16 * KPAD * 4) + ks * 32;
                const uint32_t off1 = off0 + 16 * KPAD * 4;
                uint32_t c0h, c1h, c2h, c3h, c0l, c1l, c2l, c3l;
                uint32_t d0h, d1h, d2h, d3h, d0l, d1l, d2l, d3l;
                ldsm4(c0h, c1h, c2h, c3h, kh_base + off0);
                ldsm4(c0l, c1l, c2l, c3l, kl_base + off0);
                ldsm4(d0h, d1h, d2h, d3h, kh_base + off1);
                ldsm4(d0l, d1l, d2l, d3l, kl_base + off1);
                float4* c4 = &cf[4 * nph];
                mma_f16(c4[0], qah[ks][0], qah[ks][1], qah[ks][2], qah[ks][3], c0l, c1l);
                mma_f16(c4[1], qah[ks][0], qah[ks][1], qah[ks][2], qah[ks][3], c2l, c3l);
                mma_f16(c4[2], qah[ks][0], qah[ks][1], qah[ks][2], qah[ks][3], d0l, d1l);
                mma_f16(c4[3], qah[ks][0], qah[ks][1], qah[ks][2], qah[ks][3], d2l, d3l);
                mma_f16(c4[0], qal[ks][0], qal[ks][1], qal[ks][2], qal[ks][3], c0h, c1h);
                mma_f16(c4[1], qal[ks][0], qal[ks][1], qal[ks][2], qal[ks][3], c2h, c3h);
                mma_f16(c4[2], qal[ks][0], qal[ks][1], qal[ks][2], qal[ks][3], d0h, d1h);
                mma_f16(c4[3], qal[ks][0], qal[ks][1], qal[ks][2], qal[ks][3], d2h, d3h);
                mma_f16(c4[0], qah[ks][0], qah[ks][1], qah[ks][2], qah[ks][3], c0h, c1h);
                mma_f16(c4[1], qah[ks][0], qah[ks][1], qah[ks][2], qah[ks][3], c2h, c3h);
                mma_f16(c4[2], qah[ks][0], qah[ks][1], qah[ks][2], qah[ks][3], d0h, d1h);
                mma_f16(c4[3], qah[ks][0], qah[ks][1], qah[ks][2], qah[ks][3], d2h, d3h);
            }
        }

        // ---- causal mask ----
        const int kb = kt * 64;
        if (kt >= 2 * qt) {
            const int qr0 = qbase + m0 + g;
            const int qr1 = qr0 + 8;
            #pragma unroll
            for (int nf = 0; nf < 8; nf++) {
                const int c0 = kb + nf * 8 + 2 * tg;
                if (c0 > qr0)     cf[nf].x = -INFINITY;
                if (c0 + 1 > qr0) cf[nf].y = -INFINITY;
                if (c0 > qr1)     cf[nf].z = -INFINITY;
                if (c0 + 1 > qr1) cf[nf].w = -INFINITY;
            }
        }

        // ---- row max ----
        float mt0 = -INFINITY, mt1 = -INFINITY;
        #pragma unroll
        for (int nf = 0; nf < 8; nf++) {
            mt0 = fmaxf(mt0, fmaxf(cf[nf].x, cf[nf].y));
            mt1 = fmaxf(mt1, fmaxf(cf[nf].z, cf[nf].w));
        }
        mt0 = fmaxf(mt0, __shfl_xor_sync(0xffffffffu, mt0, 1));
        mt0 = fmaxf(mt0, __shfl_xor_sync(0xffffffffu, mt0, 2));
        mt1 = fmaxf(mt1, __shfl_xor_sync(0xffffffffu, mt1, 1));
        mt1 = fmaxf(mt1, __shfl_xor_sync(0xffffffffu, mt1, 2));

        const float mn0 = fmaxf(mr0, mt0);
        const float mn1 = fmaxf(mr1, mt1);
        const float corr0 = __expf(mr0 - mn0);
        const float corr1 = __expf(mr1 - mn1);
        mr0 = mn0; mr1 = mn1;

        // ---- rescale O ----
        #pragma unroll
        for (int nf = 0; nf < 8; nf++) {
            of[nf].x *= corr0; of[nf].y *= corr0;
            of[nf].z *= corr1; of[nf].w *= corr1;
        }

        // ---- softmax + PV (2-term: P single fp16, V split exact) ----
        float s0 = 0.f, s1 = 0.f;
        #pragma unroll
        for (int ks = 0; ks < 4; ks++) {
            uint32_t ag0, ag1, ag2, ag3;
            {
                const int nf = 2 * ks;
                float p00 = __expf(cf[nf].x - mn0);
                float p01 = __expf(cf[nf].y - mn0);
                float p10 = __expf(cf[nf].z - mn1);
                float p11 = __expf(cf[nf].w - mn1);
                s0 += p00 + p01;  s1 += p10 + p11;
                ag0 = pack2h(p00, p01);
                ag1 = pack2h(p10, p11);
                float q00 = __expf(cf[nf+1].x - mn0);
                float q01 = __expf(cf[nf+1].y - mn0);
                float q10 = __expf(cf[nf+1].z - mn1);
                float q11 = __expf(cf[nf+1].w - mn1);
                s0 += q00 + q01;  s1 += q10 + q11;
                ag2 = pack2h(q00, q01);
                ag3 = pack2h(q10, q11);
            }
            #pragma unroll
            for (int fph = 0; fph < 2; fph++) {
                const uint32_t off0 = v_lane + ks * (16 * KPAD * 4) + (2 * fph) * 32;
                const uint32_t off1 = off0 + 32;
                uint32_t e0h, e1h, e2h, e3h, e0l, e1l, e2l, e3l;
                uint32_t f0h, f1h, f2h, f3h, f0l, f1l, f2l, f3l;
                ldsm4t(e0h, e1h, e2h, e3h, vh_base + off0);
                ldsm4t(e0l, e1l, e2l, e3l, vl_base + off0);
                ldsm4t(f0h, f1h, f2h, f3h, vh_base + off1);
                ldsm4t(f0l, f1l, f2l, f3l, vl_base + off1);
                float4* o4 = &of[4 * fph];
                // term P * V_l
                mma_f16(o4[0], ag0, ag1, ag2, ag3, e0l, e1l);
                mma_f16(o4[1], ag0, ag1, ag2, ag3, e2l, e3l);
                mma_f16(o4[2], ag0, ag1, ag2, ag3, f0l, f1l);
                mma_f16(o4[3], ag0, ag1, ag2, ag3, f2l, f3l);
                // term P * V_h
                mma_f16(o4[0], ag0, ag1, ag2, ag3, e0h, e1h);
                mma_f16(o4[1], ag0, ag1, ag2, ag3, e2h, e3h);
                mma_f16(o4[2], ag0, ag1, ag2, ag3, f0h, f1h);
                mma_f16(o4[3], ag0, ag1, ag2, ag3, f2h, f3h);
            }
        }
        s0 += __shfl_xor_sync(0xffffffffu, s0, 1);
        s0 += __shfl_xor_sync(0xffffffffu, s0, 2);
        s1 += __shfl_xor_sync(0xffffffffu, s1, 1);
        s1 += __shfl_xor_sync(0xffffffffu, s1, 2);
        lr0 = lr0 * corr0 + s0;
        lr1 = lr1 * corr1 + s1;

        __syncthreads();
    }

    // ---- finalize: single fp16 O ----
    const float i0 = 1.f / lr0;
    const float i1 = 1.f / lr1;
    const int r0 = qbase + m0 + g;
    const int r1 = r0 + 8;
    #pragma unroll
    for (int nf = 0; nf < 8; nf++) {
        const int c = h * HD + nf * 8 + 2 * tg;
        ((uint32_t*)oatt)[((size_t)r0 * EMB + c) >> 1] =
            pack2h(of[nf].x * i0, of[nf].y * i0);
        ((uint32_t*)oatt)[((size_t)r1 * EMB + c) >> 1] =
            pack2h(of[nf].z * i1, of[nf].w * i1);
    }
}

// ---------------------------------------------------------------------------
// kernel_launch
// ---------------------------------------------------------------------------
extern "C" void kernel_launch(void* const* d_in, const int* in_sizes, int n_in,
                              void* d_out, int out_size)
{
    const float* x    = (const float*)d_in[0];
    const float* Wqkv = (const float*)d_in[2];
    const float* bqkv = (const float*)d_in[3];
    const float* Wp   = (const float*)d_in[4];
    const float* bp   = (const float*)d_in[5];
    float* out = (float*)d_out;

    __half *xh, *xl, *wqh, *wql, *wph, *wpl, *qkvh, *qkvl, *att;
    cudaGetSymbolAddress((void**)&xh,   g_x_h);
    cudaGetSymbolAddress((void**)&xl,   g_x_l);
    cudaGetSymbolAddress((void**)&wqh,  g_wqkv_h);
    cudaGetSymbolAddress((void**)&wql,  g_wqkv_l);
    cudaGetSymbolAddress((void**)&wph,  g_wp_h);
    cudaGetSymbolAddress((void**)&wpl,  g_wp_l);
    cudaGetSymbolAddress((void**)&qkvh, g_qkv_h);
    cudaGetSymbolAddress((void**)&qkvl, g_qkv_l);
    cudaGetSymbolAddress((void**)&att,  g_att);

    // 0) prep
    split_kernel<<<SEQ * EMB / 4 / 256, 256>>>(
        (const float4*)x, (uint2*)xh, (uint2*)xl, SEQ * EMB / 4);
    {
        dim3 grid(NE3 / 32, EMB / 32);
        transpose_split_kernel<<<grid, 256>>>(Wqkv, wqh, wql, EMB, NE3);
    }
    {
        dim3 grid(EMB / 32, EMB / 32);
        transpose_split_kernel<<<grid, 256>>>(Wp, wph, wpl, EMB, EMB);
    }

    // 1) QKV projection (fp16x3) -> split fp16 qkv
    {
        cudaFuncSetAttribute(gemm_qkv_kernel,
                             cudaFuncAttributeMaxDynamicSharedMemorySize, GEMM_SMEM);
        dim3 grid(NE3 / 128, SEQ / 128);
        gemm_qkv_kernel<<<grid, 256, GEMM_SMEM>>>(
            xh, xl, wqh, wql, bqkv, qkvh, qkvl, SEQ, NE3, EMB);
    }
    // 2) causal flash attention -> single fp16 att
    {
        cudaFuncSetAttribute(flash_attn_f16_kernel,
                             cudaFuncAttributeMaxDynamicSharedMemorySize, ATT_SMEM);
        dim3 grid(SEQ / 128, NH);
        flash_attn_f16_kernel<<<grid, 256, ATT_SMEM>>>(qkvh, qkvl, att);
    }
    // 3) output projection (fp16 2-term) -> f32 out
    {
        cudaFuncSetAttribute(gemm_proj_kernel,
                             cudaFuncAttributeMaxDynamicSharedMemorySize, PROJ_SMEM);
        dim3 grid(EMB / 128, SEQ / 128);
        gemm_proj_kernel<<<grid, 256, PROJ_SMEM>>>(
            att, wph, wpl, bp, out, SEQ, EMB, EMB);
    }
}